// round 2
// baseline (speedup 1.0000x reference)
#include <cuda_runtime.h>
#include <cstdint>

// EmbeddingBagCollection: T=8 tables [V=100000, D=128] fp32, indices [T,B=4096,L=50] int32.
// out[b, t*D + d] = sum_{l} tables[t, indices[t,b,l], d]
//
// One warp per bag. Each lane owns 4 consecutive floats (float4) of the D=128 row.
// Index loads are lane-uniform (L1 broadcast); row loads are coalesced LDG.128.
// Warp ordering is table-major so a wave of resident CTAs hammers few tables -> L2 reuse.

#define T_TABLES 8
#define B_BATCH  4096
#define L_BAG    50
#define V_VOCAB  100000
#define D_DIM    128

__global__ void __launch_bounds__(256)
ebc_kernel(const int*   __restrict__ indices,
           const float* __restrict__ tables,
           float*       __restrict__ out)
{
    const int warp_id = (blockIdx.x * blockDim.x + threadIdx.x) >> 5;
    const int lane    = threadIdx.x & 31;

    if (warp_id >= T_TABLES * B_BATCH) return;

    const int t = warp_id / B_BATCH;   // table id
    const int b = warp_id % B_BATCH;   // bag id

    const int*   __restrict__ bag = indices + (size_t)warp_id * L_BAG;
    const float* __restrict__ tab = tables  + (size_t)t * V_VOCAB * D_DIM;

    float4 acc = make_float4(0.f, 0.f, 0.f, 0.f);

    // Unroll so ptxas front-batches independent idx+row loads (MLP hides DRAM latency).
    #pragma unroll 10
    for (int l = 0; l < L_BAG; ++l) {
        const int r = __ldg(&bag[l]);                    // lane-uniform broadcast
        const float4 v = *reinterpret_cast<const float4*>(
            tab + (size_t)r * D_DIM + lane * 4);
        acc.x += v.x;
        acc.y += v.y;
        acc.z += v.z;
        acc.w += v.w;
    }

    // out[b, t*D + lane*4 .. +3]
    float4* __restrict__ dst = reinterpret_cast<float4*>(
        out + (size_t)b * (T_TABLES * D_DIM) + t * D_DIM + lane * 4);
    *dst = acc;
}

extern "C" void kernel_launch(void* const* d_in, const int* in_sizes, int n_in,
                              void* d_out, int out_size)
{
    // Bind inputs by element count, not position:
    //   indices: T*B*L = 1,638,400 elements
    //   tables : T*V*D = 102,400,000 elements
    const long long N_IDX = (long long)T_TABLES * B_BATCH * L_BAG;

    const void* p0 = d_in[0];
    const void* p1 = d_in[1];
    const int*   indices;
    const float* tables;
    if ((long long)in_sizes[0] == N_IDX) {
        indices = (const int*)p0;
        tables  = (const float*)p1;
    } else {
        indices = (const int*)p1;
        tables  = (const float*)p0;
    }
    float* out = (float*)d_out;

    const int total_warps = T_TABLES * B_BATCH;            // 32768 bags
    const int threads     = 256;                           // 8 warps/block
    const int blocks      = (total_warps * 32) / threads;  // 4096 blocks

    ebc_kernel<<<blocks, threads>>>(indices, tables, out);
}

// round 3
// speedup vs baseline: 1.1234x; 1.1234x over previous
#include <cuda_runtime.h>
#include <cstdint>

// EmbeddingBagCollection: T=8 tables [V=100000, D=128] fp32, indices [T,B=4096,L=50] int32.
// out[b, t*D + d] = sum_{l} tables[t, indices[t,b,l], d]
//
// One warp per bag; lane owns float4 of the row. Table-major bag order.
// __launch_bounds__(256,3): cap 3 CTAs/SM so the resident wave covers <1 table
// (~45 MB working set, fits L2 126 MB) -> each unique row hits DRAM once.
// Chunked loads (10 idx -> 10 float4 in flight) force high MLP per warp.

#define T_TABLES 8
#define B_BATCH  4096
#define L_BAG    50
#define V_VOCAB  100000
#define D_DIM    128
#define CHUNK    10

__global__ void __launch_bounds__(256, 3)
ebc_kernel(const int*   __restrict__ indices,
           const float* __restrict__ tables,
           float*       __restrict__ out)
{
    const int warp_id = (blockIdx.x * blockDim.x + threadIdx.x) >> 5;
    const int lane    = threadIdx.x & 31;

    if (warp_id >= T_TABLES * B_BATCH) return;

    const int t = warp_id / B_BATCH;   // table id
    const int b = warp_id % B_BATCH;   // bag id

    const int*   __restrict__ bag = indices + (size_t)warp_id * L_BAG;
    const float* __restrict__ tab = tables  + (size_t)t * V_VOCAB * D_DIM
                                            + (size_t)lane * 4;

    float4 acc = make_float4(0.f, 0.f, 0.f, 0.f);

    #pragma unroll
    for (int base = 0; base < L_BAG; base += CHUNK) {
        int r[CHUNK];
        #pragma unroll
        for (int j = 0; j < CHUNK; ++j)
            r[j] = __ldg(&bag[base + j]);              // lane-uniform broadcast

        float4 v[CHUNK];
        #pragma unroll
        for (int j = 0; j < CHUNK; ++j)
            v[j] = *reinterpret_cast<const float4*>(tab + (size_t)r[j] * D_DIM);

        #pragma unroll
        for (int j = 0; j < CHUNK; ++j) {
            acc.x += v[j].x;
            acc.y += v[j].y;
            acc.z += v[j].z;
            acc.w += v[j].w;
        }
    }

    float4* __restrict__ dst = reinterpret_cast<float4*>(
        out + (size_t)b * (T_TABLES * D_DIM) + t * D_DIM + lane * 4);
    *dst = acc;
}

extern "C" void kernel_launch(void* const* d_in, const int* in_sizes, int n_in,
                              void* d_out, int out_size)
{
    const long long N_IDX = (long long)T_TABLES * B_BATCH * L_BAG;

    const int*   indices;
    const float* tables;
    if ((long long)in_sizes[0] == N_IDX) {
        indices = (const int*)d_in[0];
        tables  = (const float*)d_in[1];
    } else {
        indices = (const int*)d_in[1];
        tables  = (const float*)d_in[0];
    }
    float* out = (float*)d_out;

    const int total_warps = T_TABLES * B_BATCH;            // 32768 bags
    const int threads     = 256;                           // 8 warps/block
    const int blocks      = (total_warps * 32) / threads;  // 4096 blocks

    ebc_kernel<<<blocks, threads>>>(indices, tables, out);
}

// round 4
// speedup vs baseline: 1.1489x; 1.0227x over previous
#include <cuda_runtime.h>
#include <cstdint>

// EmbeddingBagCollection: T=8 tables [V=100000, D=128] fp32, indices [T,B=4096,L=50] int32.
// out[b, t*D + d] = sum_{l} tables[t, indices[t,b,l], d]
//
// One warp per bag; lane owns float4 of the row. Table-major bag order.
// Block stages its 8 bags' indices (1600 B) into smem with 2 coalesced loads,
// so the row-gather loop has NO global idx dependency: 10 independent LDG.128
// row loads in flight per warp at all times.
// 4 CTAs/SM: wave working set ~59 MB < L2 (126 MB) -> compulsory DRAM traffic only.

#define T_TABLES 8
#define B_BATCH  4096
#define L_BAG    50
#define V_VOCAB  100000
#define D_DIM    128
#define CHUNK    10
#define WARPS_PER_BLOCK 8

__global__ void __launch_bounds__(256, 4)
ebc_kernel(const int*   __restrict__ indices,
           const float* __restrict__ tables,
           float*       __restrict__ out)
{
    __shared__ int s_idx[WARPS_PER_BLOCK * L_BAG];   // 400 ints = 1600 B

    const int tid     = threadIdx.x;
    const int warp_id = blockIdx.x * WARPS_PER_BLOCK + (tid >> 5);
    const int lane    = tid & 31;

    // Stage this block's indices: 400 consecutive ints, coalesced.
    {
        const int* __restrict__ g = indices + (size_t)blockIdx.x * WARPS_PER_BLOCK * L_BAG;
        #pragma unroll
        for (int i = tid; i < WARPS_PER_BLOCK * L_BAG; i += 256)
            s_idx[i] = g[i];
    }
    __syncthreads();

    const int t = warp_id / B_BATCH;   // table id
    const int b = warp_id % B_BATCH;   // bag id

    const int*   bag = s_idx + (tid >> 5) * L_BAG;
    const float* __restrict__ tab = tables + (size_t)t * V_VOCAB * D_DIM
                                           + (size_t)lane * 4;

    float4 acc = make_float4(0.f, 0.f, 0.f, 0.f);

    #pragma unroll
    for (int base = 0; base < L_BAG; base += CHUNK) {
        float4 v[CHUNK];
        #pragma unroll
        for (int j = 0; j < CHUNK; ++j) {
            const int r = bag[base + j];               // LDS broadcast, cheap
            v[j] = *reinterpret_cast<const float4*>(tab + (size_t)r * D_DIM);
        }
        #pragma unroll
        for (int j = 0; j < CHUNK; ++j) {
            acc.x += v[j].x;
            acc.y += v[j].y;
            acc.z += v[j].z;
            acc.w += v[j].w;
        }
    }

    float4* __restrict__ dst = reinterpret_cast<float4*>(
        out + (size_t)b * (T_TABLES * D_DIM) + t * D_DIM + lane * 4);
    *dst = acc;
}

extern "C" void kernel_launch(void* const* d_in, const int* in_sizes, int n_in,
                              void* d_out, int out_size)
{
    const long long N_IDX = (long long)T_TABLES * B_BATCH * L_BAG;

    const int*   indices;
    const float* tables;
    if ((long long)in_sizes[0] == N_IDX) {
        indices = (const int*)d_in[0];
        tables  = (const float*)d_in[1];
    } else {
        indices = (const int*)d_in[1];
        tables  = (const float*)d_in[0];
    }
    float* out = (float*)d_out;

    const int total_warps = T_TABLES * B_BATCH;              // 32768 bags
    const int blocks      = total_warps / WARPS_PER_BLOCK;   // 4096 blocks

    ebc_kernel<<<blocks, 256>>>(indices, tables, out);
}